// round 4
// baseline (speedup 1.0000x reference)
#include <cuda_runtime.h>
#include <stdint.h>

// ParallelTransport: out[e, c, :] = R(rho[e]) @ x[row[e], c, :]
// x: (1, N, 32, 2) fp32 ; edge_index: (2, E) int32 ; rho: (E,) fp32
// out: (1, E, 32, 2) fp32
//
// R4: 256-bit LDG/STG (sm_100+ v8.f32), 8 threads per edge (32 B each),
// ITER=4 batched phases -> 128 B of gather traffic in flight per thread.
// Streaming stores keep the 12.8 MB x table resident in L2.

struct F8 { float a, b, c, d, e, f, g, h; };

__device__ __forceinline__ F8 ldg256(const float* p) {
    F8 r;
    asm volatile("ld.global.nc.v8.f32 {%0,%1,%2,%3,%4,%5,%6,%7}, [%8];"
                 : "=f"(r.a), "=f"(r.b), "=f"(r.c), "=f"(r.d),
                   "=f"(r.e), "=f"(r.f), "=f"(r.g), "=f"(r.h)
                 : "l"(p));
    return r;
}

__device__ __forceinline__ void stg256_cs(float* p, const F8& r) {
    asm volatile("st.global.cs.v8.f32 [%0], {%1,%2,%3,%4,%5,%6,%7,%8};"
                 :: "l"(p),
                    "f"(r.a), "f"(r.b), "f"(r.c), "f"(r.d),
                    "f"(r.e), "f"(r.f), "f"(r.g), "f"(r.h)
                 : "memory");
}

#define ITER 4

__global__ void __launch_bounds__(256)
pt_kernel(const float* __restrict__ x,
          const int* __restrict__ row,
          const float* __restrict__ rho,
          float* __restrict__ out,
          long long total8 /* E * 8 slots of 8 floats */)
{
    long long base = (long long)blockIdx.x * (256 * ITER) + threadIdx.x;

    long long slot[ITER];
    int   r[ITER];
    float rv[ITER];
    F8    v[ITER];

    // Phase 1: index + rho loads (broadcast within 8-lane groups)
    #pragma unroll
    for (int i = 0; i < ITER; i++) {
        slot[i] = base + (long long)i * 256;
        long long e = slot[i] >> 3;
        bool ok = slot[i] < total8;
        r[i]  = ok ? __ldg(&row[e]) : 0;
        rv[i] = ok ? __ldg(&rho[e]) : 0.0f;
    }

    // Phase 2: dependent 256-bit gathers — 4 independent chains, 128 B in flight
    #pragma unroll
    for (int i = 0; i < ITER; i++) {
        int sub = (int)(slot[i] & 7);
        v[i] = ldg256(x + (long long)r[i] * 64 + sub * 8);
    }

    // Phase 3: rotate + streaming 256-bit store
    #pragma unroll
    for (int i = 0; i < ITER; i++) {
        if (slot[i] >= total8) continue;
        float s, c;
        __sincosf(rv[i], &s, &c);
        F8 o;
        o.a = fmaf(c, v[i].a, -s * v[i].b);
        o.b = fmaf(s, v[i].a,  c * v[i].b);
        o.c = fmaf(c, v[i].c, -s * v[i].d);
        o.d = fmaf(s, v[i].c,  c * v[i].d);
        o.e = fmaf(c, v[i].e, -s * v[i].f);
        o.f = fmaf(s, v[i].e,  c * v[i].f);
        o.g = fmaf(c, v[i].g, -s * v[i].h);
        o.h = fmaf(s, v[i].g,  c * v[i].h);
        stg256_cs(out + slot[i] * 8, o);
    }
}

extern "C" void kernel_launch(void* const* d_in, const int* in_sizes, int n_in,
                              void* d_out, int out_size)
{
    const float* x    = (const float*)d_in[0];
    const int*   eidx = (const int*)d_in[1];   // (2, E): first E entries = row
    const float* rho  = (const float*)d_in[2];

    long long E = in_sizes[2];
    long long total8 = E * 8;                  // 32 B slots

    int threads = 256;
    long long per_block = (long long)threads * ITER;
    long long blocks = (total8 + per_block - 1) / per_block;

    pt_kernel<<<(unsigned)blocks, threads>>>(
        x, eidx, rho, (float*)d_out, total8);
}

// round 5
// speedup vs baseline: 1.1495x; 1.1495x over previous
#include <cuda_runtime.h>
#include <stdint.h>

// ParallelTransport: out[e, c, :] = R(rho[e]) @ x[row[e], c, :]
// x: (1, N, 32, 2) fp32 ; edge_index: (2, E) int32 ; rho: (E,) fp32
// out: (1, E, 32, 2) fp32
//
// R5: R3 structure (16 thr/edge, float4 each), ITER=6 batched phases,
// all-32-bit slot arithmetic (total = E*16 < 2^31). Streaming stores
// protect the L2-resident 12.8 MB x table.

#define ITER 6

__global__ void __launch_bounds__(256)
pt_kernel(const float* __restrict__ x,
          const int* __restrict__ row,
          const float* __restrict__ rho,
          float4* __restrict__ out,
          unsigned total /* E * 16 float4 slots, < 2^31 */)
{
    unsigned base = blockIdx.x * (256u * ITER) + threadIdx.x;

    int    r[ITER];
    float  rv[ITER];
    float4 v[ITER];

    // Phase 1: index + rho loads (L1-broadcast within 16-lane groups)
    #pragma unroll
    for (int i = 0; i < ITER; i++) {
        unsigned slot = base + i * 256u;
        unsigned e = slot >> 4;
        bool ok = slot < total;
        r[i]  = ok ? __ldg(&row[e]) : 0;
        rv[i] = ok ? __ldg(&rho[e]) : 0.0f;
    }

    // Phase 2: dependent gathers — ITER independent chains in flight
    #pragma unroll
    for (int i = 0; i < ITER; i++) {
        unsigned slot = base + i * 256u;
        unsigned sub  = slot & 15u;
        const float4* xp =
            reinterpret_cast<const float4*>(x) + ((unsigned)r[i] * 16u + sub);
        v[i] = __ldg(xp);
    }

    // Phase 3: rotate + streaming store
    #pragma unroll
    for (int i = 0; i < ITER; i++) {
        unsigned slot = base + i * 256u;
        if (slot >= total) continue;
        float s, c;
        __sincosf(rv[i], &s, &c);
        float4 o;
        o.x = fmaf(c, v[i].x, -s * v[i].y);
        o.y = fmaf(s, v[i].x,  c * v[i].y);
        o.z = fmaf(c, v[i].z, -s * v[i].w);
        o.w = fmaf(s, v[i].z,  c * v[i].w);
        __stcs(&out[slot], o);
    }
}

extern "C" void kernel_launch(void* const* d_in, const int* in_sizes, int n_in,
                              void* d_out, int out_size)
{
    const float* x    = (const float*)d_in[0];
    const int*   eidx = (const int*)d_in[1];   // (2, E): first E entries = row
    const float* rho  = (const float*)d_in[2];

    unsigned E = (unsigned)in_sizes[2];
    unsigned total = E * 16u;                  // float4 slots

    int threads = 256;
    unsigned per_block = threads * ITER;
    unsigned blocks = (total + per_block - 1) / per_block;

    pt_kernel<<<blocks, threads>>>(x, eidx, rho, (float4*)d_out, total);
}

// round 6
// speedup vs baseline: 1.1693x; 1.0172x over previous
#include <cuda_runtime.h>
#include <stdint.h>

// ParallelTransport: out[e, c, :] = R(rho[e]) @ x[row[e], c, :]
// x: (1, N, 32, 2) fp32 ; edge_index: (2, E) int32 ; rho: (E,) fp32
// out: (1, E, 32, 2) fp32
//
// R6: R3 structure (16 thr/edge, float4 each, ITER=4 batched phases) with
// 32-bit slot arithmetic and NO bounds checks in the main kernel (grid covers
// exactly blocks*1024 slots; a tail kernel handles the remainder, which is
// empty for E=1.6M). Streaming stores protect the L2-resident x table.

#define ITER 4
#define TPB  256

__global__ void __launch_bounds__(TPB)
pt_kernel(const float* __restrict__ x,
          const int* __restrict__ row,
          const float* __restrict__ rho,
          float4* __restrict__ out)
{
    unsigned base = blockIdx.x * (TPB * ITER) + threadIdx.x;

    int    r[ITER];
    float  rv[ITER];
    float4 v[ITER];

    // Phase 1: index + rho loads (L1-broadcast within 16-lane groups)
    #pragma unroll
    for (int i = 0; i < ITER; i++) {
        unsigned e = (base + i * TPB) >> 4;
        r[i]  = __ldg(&row[e]);
        rv[i] = __ldg(&rho[e]);
    }

    // Phase 2: dependent gathers — 4 independent chains in flight
    #pragma unroll
    for (int i = 0; i < ITER; i++) {
        unsigned sub = (base + i * TPB) & 15u;
        v[i] = __ldg(reinterpret_cast<const float4*>(x)
                     + ((unsigned)r[i] * 16u + sub));
    }

    // Phase 3: rotate + streaming store
    #pragma unroll
    for (int i = 0; i < ITER; i++) {
        float s, c;
        __sincosf(rv[i], &s, &c);
        float4 o;
        o.x = fmaf(c, v[i].x, -s * v[i].y);
        o.y = fmaf(s, v[i].x,  c * v[i].y);
        o.z = fmaf(c, v[i].z, -s * v[i].w);
        o.w = fmaf(s, v[i].z,  c * v[i].w);
        __stcs(&out[base + i * TPB], o);
    }
}

// Tail: handles slots [start, total) — only launched if total % (TPB*ITER) != 0
__global__ void __launch_bounds__(TPB)
pt_tail_kernel(const float* __restrict__ x,
               const int* __restrict__ row,
               const float* __restrict__ rho,
               float4* __restrict__ out,
               unsigned start, unsigned total)
{
    unsigned slot = start + blockIdx.x * TPB + threadIdx.x;
    if (slot >= total) return;
    unsigned e = slot >> 4, sub = slot & 15u;
    int   r  = __ldg(&row[e]);
    float rv = __ldg(&rho[e]);
    float s, c;
    __sincosf(rv, &s, &c);
    float4 v = __ldg(reinterpret_cast<const float4*>(x) + ((unsigned)r * 16u + sub));
    float4 o;
    o.x = fmaf(c, v.x, -s * v.y);
    o.y = fmaf(s, v.x,  c * v.y);
    o.z = fmaf(c, v.z, -s * v.w);
    o.w = fmaf(s, v.z,  c * v.w);
    __stcs(&out[slot], o);
}

extern "C" void kernel_launch(void* const* d_in, const int* in_sizes, int n_in,
                              void* d_out, int out_size)
{
    const float* x    = (const float*)d_in[0];
    const int*   eidx = (const int*)d_in[1];   // (2, E): first E entries = row
    const float* rho  = (const float*)d_in[2];

    unsigned E = (unsigned)in_sizes[2];
    unsigned total = E * 16u;                  // float4 slots
    unsigned per_block = TPB * ITER;
    unsigned full_blocks = total / per_block;
    unsigned covered = full_blocks * per_block;

    if (full_blocks)
        pt_kernel<<<full_blocks, TPB>>>(x, eidx, rho, (float4*)d_out);

    if (covered < total) {
        unsigned rem = total - covered;
        unsigned tb  = (rem + TPB - 1) / TPB;
        pt_tail_kernel<<<tb, TPB>>>(x, eidx, rho, (float4*)d_out, covered, total);
    }
}